// round 4
// baseline (speedup 1.0000x reference)
#include <cuda_runtime.h>
#include <cuda_bf16.h>
#include <math.h>
#include <stdint.h>

// Problem constants
#define Bn  32
#define Cc  80
#define TXn 512
#define TYn 2048
#define K2  160          // stacked K: [scale(80); mean*scale(80)]
#define NEGV (-1e9f)
#define LOG2PI 1.8378770664093453f
#define PHC 8            // columns per fwd phase

// Output layout (flat f32, reference return order)
#define Z_OFF        0
#define YMEAN_OFF    (Bn*Cc*TYn)
#define YLOG_OFF     (2*Bn*Cc*TYn)
#define ATTN_OFF     (3*Bn*Cc*TYn)
#define ODUR_OFF     (ATTN_OFF + Bn*TYn*TXn)
#define OADUR_OFF    (ODUR_OFF + Bn*TXn)

// -------------------- scratch (__device__ globals) --------------------------
__device__ float    g_W[Bn*K2*TXn];              // [b][k][x]
__device__ float    g_Z[Bn*K2*TYn];              // [b][k][y]
__device__ float    g_rowA[Bn*TXn];              // logp1+logp4 per (b,x)
__device__ float    g_logpT[(size_t)Bn*TYn*TXn]; // 134 MB [b][y][x]
__device__ unsigned g_dbits[(size_t)Bn*TYn*32];  // dir bits: 32 words/col, 16 bits/word
__device__ int      g_xy[Bn*TYn];                // alignment index per (b,y)
__device__ int      g_cnt[Bn*TXn];               // per-x duration counts

// -------------------- K1: per-(b,x) prep -------------------------------------
__global__ void prepx_kernel(const float* __restrict__ om,
                             const float* __restrict__ ols,
                             const float* __restrict__ odur,
                             float* __restrict__ out)
{
    int i = blockIdx.x * blockDim.x + threadIdx.x;
    if (i >= Bn*TXn) return;
    int b = i / TXn, x = i % TXn;
    const float* omb = om  + (size_t)b*Cc*TXn + x;
    const float* olb = ols + (size_t)b*Cc*TXn + x;
    float* wS = g_W + (size_t)b*K2*TXn + x;
    float sa = 0.f;
    #pragma unroll 4
    for (int c = 0; c < Cc; c++) {
        float l  = olb[(size_t)c*TXn];
        float sc = expf(-2.f*l);
        float m  = omb[(size_t)c*TXn];
        wS[(size_t)c*TXn]        = sc;
        wS[(size_t)(Cc+c)*TXn]   = m*sc;
        sa += -0.5f*LOG2PI - l - 0.5f*m*m*sc;
    }
    g_rowA[i] = sa;
    g_cnt[i]  = 0;
    out[ODUR_OFF + i] = odur[i];
}

// -------------------- K2: z masking + Z matrix --------------------------------
__global__ void prepz_kernel(const float* __restrict__ z,
                             const int* __restrict__ yl,
                             float* __restrict__ out)
{
    int i = blockIdx.x * blockDim.x + threadIdx.x;
    if (i >= Bn*Cc*TYn) return;
    int b = i / (Cc*TYn);
    int r = i % (Cc*TYn);
    int c = r / TYn;
    int y = r % TYn;
    float zv = z[i];
    if (y >= yl[b]) zv = 0.f;
    out[Z_OFF + i] = zv;
    size_t zb = (size_t)b*K2*TYn;
    g_Z[zb + (size_t)c*TYn + y]      = -0.5f*zv*zv;
    g_Z[zb + (size_t)(Cc+c)*TYn + y] = zv;
}

// -------------------- K3: logp GEMM (128x128 tile, 256 thr, 8x8/thr) ----------
__global__ void __launch_bounds__(256, 2)
gemm_kernel(const int* __restrict__ xl, const int* __restrict__ yl)
{
    int b  = blockIdx.z;
    int x0 = blockIdx.x * 128;
    int y0 = blockIdx.y * 128;
    int xlen = xl[b], ylen = yl[b];
    if (x0 >= xlen || y0 >= ylen) return;

    __shared__ float zs[16][128];   // k x y
    __shared__ float ws[16][128];   // k x x

    int tid  = threadIdx.x;
    int lrow = tid >> 4;            // 0..15
    int lcol = (tid & 15) << 3;     // 0..120
    int ty   = tid >> 4;            // 0..15
    int tx   = tid & 15;            // 0..15

    const float* Zb = g_Z + (size_t)b*K2*TYn;
    const float* Wb = g_W + (size_t)b*K2*TXn;

    float acc[8][8] = {};

    for (int k0 = 0; k0 < K2; k0 += 16) {
        const float* zp = Zb + (size_t)(k0+lrow)*TYn + y0 + lcol;
        const float* wp = Wb + (size_t)(k0+lrow)*TXn + x0 + lcol;
        *(float4*)&zs[lrow][lcol]   = *(const float4*)zp;
        *(float4*)&zs[lrow][lcol+4] = *(const float4*)(zp+4);
        *(float4*)&ws[lrow][lcol]   = *(const float4*)wp;
        *(float4*)&ws[lrow][lcol+4] = *(const float4*)(wp+4);
        __syncthreads();
        #pragma unroll
        for (int k = 0; k < 16; k++) {
            float4 z0 = *(float4*)&zs[k][ty<<3];
            float4 z1 = *(float4*)&zs[k][(ty<<3)+4];
            float4 w0 = *(float4*)&ws[k][tx<<3];
            float4 w1 = *(float4*)&ws[k][(tx<<3)+4];
            float za[8] = {z0.x,z0.y,z0.z,z0.w,z1.x,z1.y,z1.z,z1.w};
            float wa[8] = {w0.x,w0.y,w0.z,w0.w,w1.x,w1.y,w1.z,w1.w};
            #pragma unroll
            for (int i = 0; i < 8; i++)
                #pragma unroll
                for (int j = 0; j < 8; j++)
                    acc[i][j] += za[i]*wa[j];
        }
        __syncthreads();
    }

    float ra[8];
    #pragma unroll
    for (int j = 0; j < 8; j++)
        ra[j] = g_rowA[b*TXn + x0 + (tx<<3) + j];

    #pragma unroll
    for (int i = 0; i < 8; i++) {
        int y = y0 + (ty<<3) + i;
        float* op = g_logpT + ((size_t)b*TYn + y)*TXn + x0 + (tx<<3);
        float4 o0, o1;
        float* p0 = (float*)&o0; float* p1 = (float*)&o1;
        bool yok = (y < ylen);
        #pragma unroll
        for (int j = 0; j < 4; j++) {
            int xa = x0 + (tx<<3) + j;
            int xb = xa + 4;
            p0[j] = (yok && xa < xlen) ? (acc[i][j]   + ra[j])   : 0.f;
            p1[j] = (yok && xb < xlen) ? (acc[i][j+4] + ra[j+4]) : 0.f;
        }
        *(float4*)op       = o0;
        *(float4*)(op + 4) = o1;
    }
}

// -------------------- K4: forward Viterbi (2 warps per batch, skewed) ----------
// warp 0: x in [0,256), warp 1: x in [256,512), 8 x per lane.
// warp 1 runs one PHC-column phase behind warp 0; boundary v[255] values are
// published through smem ring[], made visible by the per-phase __syncthreads.
__global__ void __launch_bounds__(64)
fwd_kernel(const int* __restrict__ xl, const int* __restrict__ yl)
{
    int b    = blockIdx.x;
    int tid  = threadIdx.x;
    int wp   = tid >> 5;           // 0 or 1
    int lane = tid & 31;
    int xlen = xl[b], ylen = yl[b];

    __shared__ float ring[TYn + 1];   // ring[j] = v[255] entering column j

    int xb = (wp << 8) + lane * 8;    // this lane's first x

    // force-stay bits (8 per lane) for x >= xlen
    unsigned force8;
    {
        int rel = xlen - xb;
        if (rel <= 0)      force8 = 0xFFu;
        else if (rel < 8)  force8 = (0xFFu << rel) & 0xFFu;
        else               force8 = 0u;
    }

    float v[8];
    #pragma unroll
    for (int i = 0; i < 8; i++) v[i] = 0.f;

    if (tid == 0) ring[0] = 0.f;

    const float* base = g_logpT + (size_t)b*TYn*TXn + xb;
    // dbits: 16-bit payload per word; even lane writes word (xb>>4)
    unsigned* dwp = g_dbits + (size_t)b*TYn*32 + (xb >> 4);

    // 8-column register prefetch ring (2 float4 per column)
    float4 cb[PHC][2];
    #pragma unroll
    for (int d = 0; d < PHC; d++) {
        if (d < ylen) {
            cb[d][0] = *(const float4*)(base + (size_t)d*TXn);
            cb[d][1] = *(const float4*)(base + (size_t)d*TXn + 4);
        }
    }

    int nph = (ylen + PHC - 1) / PHC;

    for (int P = 0; P <= nph; P++) {
        int q = P - wp;                       // my work phase this step
        if (q >= 0 && q < nph) {
            int j0 = q * PHC;
            int j1 = min(j0 + PHC, ylen);
            float rb[PHC];
            if (wp == 1) {
                #pragma unroll
                for (int d = 0; d < PHC; d++) rb[d] = ring[j0 + d];
            }
            #pragma unroll
            for (int d = 0; d < PHC; d++) {
                int j = j0 + d;
                if (j < j1) {
                    float c[8];
                    *(float4*)&c[0] = cb[d][0];
                    *(float4*)&c[4] = cb[d][1];
                    int jn = j + PHC;
                    if (jn < ylen) {
                        cb[d][0] = *(const float4*)(base + (size_t)jn*TXn);
                        cb[d][1] = *(const float4*)(base + (size_t)jn*TXn + 4);
                    }

                    float left = __shfl_up_sync(0xFFFFFFFFu, v[7], 1);
                    if (lane == 0) left = (wp == 0) ? NEGV : rb[d];

                    float nv[8];
                    unsigned bits = 0u;
                    float pv = left;
                    #pragma unroll
                    for (int i = 0; i < 8; i++) {
                        bool  di = v[i] >= pv;
                        float vm = fmaxf(v[i], pv);
                        nv[i] = vm + c[i];
                        bits |= di ? (1u << i) : 0u;
                        pv = v[i];
                    }
                    if (j < xlen - 1) {       // ramp: x > j forced to NEG
                        #pragma unroll
                        for (int i = 0; i < 8; i++)
                            if (xb + i > j) nv[i] = NEGV;
                    }
                    #pragma unroll
                    for (int i = 0; i < 8; i++) v[i] = nv[i];

                    bits |= force8;
                    unsigned other = __shfl_xor_sync(0xFFFFFFFFu, bits, 1);
                    if ((lane & 1) == 0) dwp[(size_t)j*32] = bits | (other << 8);
                    if (wp == 0 && lane == 31) ring[j + 1] = v[7];
                }
            }
        }
        __syncthreads();
    }
}

// -------------------- K5: backtrack + count (1 warp per batch, 16-bit words) ---
__global__ void __launch_bounds__(32)
bwd_kernel(const int* __restrict__ xl, const int* __restrict__ yl)
{
    int b = blockIdx.x, lane = threadIdx.x;
    int xlen = xl[b], ylen = yl[b];

    for (int j = ylen + lane; j < TYn; j += 32) g_xy[b*TYn + j] = 0;

    int idx = xlen - 1;
    for (int jhi = ylen - 1; jhi >= 0; jhi -= 32) {
        int steps = min(32, jhi + 1);
        int j = jhi - lane;
        int w0 = idx >> 4;
        unsigned d0 = 0xFFFFu, d1 = 0xFFFFu, d2 = 0xFFFFu;
        if (lane < steps) {
            const unsigned* p = g_dbits + ((size_t)b*TYn + j)*32;
            d0 = p[w0];
            if (w0 >= 1) d1 = p[w0-1];
            if (w0 >= 2) d2 = p[w0-2];
        }
        int myidx = 0;
        for (int s = 0; s < steps; s++) {
            int wsel = w0 - (idx >> 4);
            unsigned sel  = (wsel == 0) ? d0 : ((wsel == 1) ? d1 : d2);
            unsigned word = __shfl_sync(0xFFFFFFFFu, sel, s);
            if (lane == s) myidx = idx;
            idx += (int)((word >> (idx & 15)) & 1u) - 1;
        }
        if (lane < steps) {
            g_xy[b*TYn + jhi - lane] = myidx;
            atomicAdd(&g_cnt[b*TXn + myidx], 1);
        }
    }
}

// -------------------- K6: y_mean / y_log_scale gathers -------------------------
__global__ void gather_kernel(const float* __restrict__ om,
                              const float* __restrict__ ols,
                              const int* __restrict__ yl,
                              float* __restrict__ out)
{
    int i = blockIdx.x * blockDim.x + threadIdx.x;
    if (i >= Bn*Cc*TYn) return;
    int b = i / (Cc*TYn);
    int r = i % (Cc*TYn);
    int c = r / TYn;
    int y = r % TYn;
    float m = 0.f, s = 0.f;
    if (y < yl[b]) {
        int x = g_xy[b*TYn + y];
        m = om [(size_t)(b*Cc + c)*TXn + x];
        s = ols[(size_t)(b*Cc + c)*TXn + x];
    }
    out[YMEAN_OFF + i] = m;
    out[YLOG_OFF  + i] = s;
}

// -------------------- K7: attn_out (zero + one-hot scatter) --------------------
__global__ void attn_kernel(const int* __restrict__ yl, float* __restrict__ out)
{
    int y = blockIdx.x, b = blockIdx.y, t = threadIdx.x;
    int xi = (y < yl[b]) ? g_xy[b*TYn + y] : -1;
    int x4 = t << 2;
    float4 r = make_float4(0.f, 0.f, 0.f, 0.f);
    if (xi >= x4 && xi < x4 + 4) ((float*)&r)[xi - x4] = 1.0f;
    *(float4*)&out[ATTN_OFF + ((size_t)b*TYn + y)*TXn + x4] = r;
}

// -------------------- K8: o_attn_dur --------------------------------------------
__global__ void dur_kernel(const int* __restrict__ xl, float* __restrict__ out)
{
    int i = blockIdx.x * blockDim.x + threadIdx.x;
    if (i >= Bn*TXn) return;
    int b = i / TXn, x = i % TXn;
    out[OADUR_OFF + i] = (x < xl[b]) ? log1pf((float)g_cnt[i]) : 0.f;
}

// -------------------- launch (single stream) -------------------------------------
extern "C" void kernel_launch(void* const* d_in, const int* in_sizes, int n_in,
                              void* d_out, int out_size)
{
    const float* om   = (const float*)d_in[0];
    const float* ols  = (const float*)d_in[1];
    const float* odur = (const float*)d_in[2];
    const float* z    = (const float*)d_in[3];
    const int*   xlen = (const int*)  d_in[4];
    const int*   ylen = (const int*)  d_in[5];
    float* out = (float*)d_out;

    prepx_kernel<<<(Bn*TXn + 255)/256, 256>>>(om, ols, odur, out);
    prepz_kernel<<<(Bn*Cc*TYn + 255)/256, 256>>>(z, ylen, out);
    gemm_kernel<<<dim3(TXn/128, TYn/128, Bn), 256>>>(xlen, ylen);
    fwd_kernel<<<Bn, 64>>>(xlen, ylen);
    bwd_kernel<<<Bn, 32>>>(xlen, ylen);
    gather_kernel<<<(Bn*Cc*TYn + 255)/256, 256>>>(om, ols, ylen, out);
    attn_kernel<<<dim3(TYn, Bn), 128>>>(ylen, out);
    dur_kernel<<<(Bn*TXn + 255)/256, 256>>>(xlen, out);
}

// round 6
// speedup vs baseline: 1.6512x; 1.6512x over previous
#include <cuda_runtime.h>
#include <cuda_bf16.h>
#include <math.h>
#include <stdint.h>

// Problem constants
#define Bn  32
#define Cc  80
#define TXn 512
#define TYn 2048
#define K2  160          // stacked K: [scale(80); mean*scale(80)]
#define NEGV (-1e9f)
#define LOG2PI 1.8378770664093453f

// Output layout (flat f32, reference return order)
#define Z_OFF        0
#define YMEAN_OFF    (Bn*Cc*TYn)
#define YLOG_OFF     (2*Bn*Cc*TYn)
#define ATTN_OFF     (3*Bn*Cc*TYn)
#define ODUR_OFF     (ATTN_OFF + Bn*TYn*TXn)
#define OADUR_OFF    (ODUR_OFF + Bn*TXn)

// -------------------- scratch (__device__ globals) --------------------------
__device__ float    g_W[Bn*K2*TXn];              // [b][k][x]
__device__ float    g_Z[Bn*K2*TYn];              // [b][k][y]
__device__ float    g_rowA[Bn*TXn];              // logp1+logp4 per (b,x)
__device__ float    g_logpT[(size_t)Bn*TYn*TXn]; // 134 MB [b][y][x]
__device__ unsigned g_dbits[(size_t)Bn*TYn*16];  // dir bits, 32 per warp-word
__device__ int      g_xy[Bn*TYn];                // alignment index per (b,y)
__device__ int      g_cnt[Bn*TXn];               // per-x duration counts

// -------------------- K1: per-(b,x) prep -------------------------------------
__global__ void prepx_kernel(const float* __restrict__ om,
                             const float* __restrict__ ols,
                             const float* __restrict__ odur,
                             float* __restrict__ out)
{
    int i = blockIdx.x * blockDim.x + threadIdx.x;
    if (i >= Bn*TXn) return;
    int b = i / TXn, x = i % TXn;
    const float* omb = om  + (size_t)b*Cc*TXn + x;
    const float* olb = ols + (size_t)b*Cc*TXn + x;
    float* wS = g_W + (size_t)b*K2*TXn + x;
    float sa = 0.f;
    #pragma unroll 4
    for (int c = 0; c < Cc; c++) {
        float l  = olb[(size_t)c*TXn];
        float sc = expf(-2.f*l);
        float m  = omb[(size_t)c*TXn];
        wS[(size_t)c*TXn]        = sc;
        wS[(size_t)(Cc+c)*TXn]   = m*sc;
        sa += -0.5f*LOG2PI - l - 0.5f*m*m*sc;
    }
    g_rowA[i] = sa;
    g_cnt[i]  = 0;
    out[ODUR_OFF + i] = odur[i];
}

// -------------------- K2: z masking + Z matrix --------------------------------
__global__ void prepz_kernel(const float* __restrict__ z,
                             const int* __restrict__ yl,
                             float* __restrict__ out)
{
    int i = blockIdx.x * blockDim.x + threadIdx.x;
    if (i >= Bn*Cc*TYn) return;
    int b = i / (Cc*TYn);
    int r = i % (Cc*TYn);
    int c = r / TYn;
    int y = r % TYn;
    float zv = z[i];
    if (y >= yl[b]) zv = 0.f;
    out[Z_OFF + i] = zv;
    size_t zb = (size_t)b*K2*TYn;
    g_Z[zb + (size_t)c*TYn + y]      = -0.5f*zv*zv;
    g_Z[zb + (size_t)(Cc+c)*TYn + y] = zv;
}

// -------------------- K3: logp GEMM (128x128 tile, 256 thr, 8x8/thr) ----------
__global__ void __launch_bounds__(256, 2)
gemm_kernel(const int* __restrict__ xl, const int* __restrict__ yl)
{
    int b  = blockIdx.z;
    int x0 = blockIdx.x * 128;
    int y0 = blockIdx.y * 128;
    int xlen = xl[b], ylen = yl[b];
    if (x0 >= xlen || y0 >= ylen) return;

    __shared__ float zs[16][128];   // k x y
    __shared__ float ws[16][128];   // k x x

    int tid  = threadIdx.x;
    int lrow = tid >> 4;            // 0..15
    int lcol = (tid & 15) << 3;     // 0..120
    int ty   = tid >> 4;            // 0..15
    int tx   = tid & 15;            // 0..15

    const float* Zb = g_Z + (size_t)b*K2*TYn;
    const float* Wb = g_W + (size_t)b*K2*TXn;

    float acc[8][8] = {};

    for (int k0 = 0; k0 < K2; k0 += 16) {
        const float* zp = Zb + (size_t)(k0+lrow)*TYn + y0 + lcol;
        const float* wp = Wb + (size_t)(k0+lrow)*TXn + x0 + lcol;
        *(float4*)&zs[lrow][lcol]   = *(const float4*)zp;
        *(float4*)&zs[lrow][lcol+4] = *(const float4*)(zp+4);
        *(float4*)&ws[lrow][lcol]   = *(const float4*)wp;
        *(float4*)&ws[lrow][lcol+4] = *(const float4*)(wp+4);
        __syncthreads();
        #pragma unroll
        for (int k = 0; k < 16; k++) {
            float4 z0 = *(float4*)&zs[k][ty<<3];
            float4 z1 = *(float4*)&zs[k][(ty<<3)+4];
            float4 w0 = *(float4*)&ws[k][tx<<3];
            float4 w1 = *(float4*)&ws[k][(tx<<3)+4];
            float za[8] = {z0.x,z0.y,z0.z,z0.w,z1.x,z1.y,z1.z,z1.w};
            float wa[8] = {w0.x,w0.y,w0.z,w0.w,w1.x,w1.y,w1.z,w1.w};
            #pragma unroll
            for (int i = 0; i < 8; i++)
                #pragma unroll
                for (int j = 0; j < 8; j++)
                    acc[i][j] += za[i]*wa[j];
        }
        __syncthreads();
    }

    float ra[8];
    #pragma unroll
    for (int j = 0; j < 8; j++)
        ra[j] = g_rowA[b*TXn + x0 + (tx<<3) + j];

    #pragma unroll
    for (int i = 0; i < 8; i++) {
        int y = y0 + (ty<<3) + i;
        float* op = g_logpT + ((size_t)b*TYn + y)*TXn + x0 + (tx<<3);
        float4 o0, o1;
        float* p0 = (float*)&o0; float* p1 = (float*)&o1;
        bool yok = (y < ylen);
        #pragma unroll
        for (int j = 0; j < 4; j++) {
            int xa = x0 + (tx<<3) + j;
            int xb = xa + 4;
            p0[j] = (yok && xa < xlen) ? (acc[i][j]   + ra[j])   : 0.f;
            p1[j] = (yok && xb < xlen) ? (acc[i][j+4] + ra[j+4]) : 0.f;
        }
        *(float4*)op       = o0;
        *(float4*)(op + 4) = o1;
    }
}

// -------------------- K4: forward Viterbi (16 warps, skewed wavefront) ---------
// 512 threads, 1 x per thread. Warp w processes column-phase q = P - w (8
// columns) at global phase P. Boundary values live in PER-WARP slots:
//   sbuf[w][(j+1) & 31]  = v[32w+31] after column j   (written by warp w)
//   warp w reads sbuf[w-1][j & 31]                    (neighbor before column j)
// Producer writes land >=1 barrier before the consumer read; slot reuse is 4
// phases later. One __syncthreads per 8 columns.
__global__ void __launch_bounds__(512)
fwd_kernel(const int* __restrict__ xl, const int* __restrict__ yl)
{
    int b    = blockIdx.x;
    int x    = threadIdx.x;
    int w    = x >> 5, lane = x & 31;
    int xlen = xl[b], ylen = yl[b];

    __shared__ float sbuf[16][32];   // [warp][column mod 32]

    // force-stay bits for x >= xlen (per warp word)
    unsigned force;
    {
        int rel = xlen - (w << 5);
        if (rel <= 0)      force = 0xFFFFFFFFu;
        else if (rel < 32) force = 0xFFFFFFFFu << rel;
        else               force = 0u;
    }

    float v = 0.f;
    const float* base  = g_logpT + (size_t)b*TYn*TXn + x;
    unsigned*    dbase = g_dbits + (size_t)b*TYn*16 + w;

    int nph = (ylen + 7) >> 3;

    // register prefetch: cc = my current phase, cn = next phase
    float cc[8], cn[8];
    #pragma unroll
    for (int d = 0; d < 8; d++)
        cc[d] = (d < ylen) ? base[(size_t)d*TXn] : 0.f;
    #pragma unroll
    for (int d = 0; d < 8; d++)
        cn[d] = (8 + d < ylen) ? base[(size_t)(8 + d)*TXn] : 0.f;

    if (lane == 0) sbuf[w][0] = 0.f;   // initial boundary (v=0 before column 0)
    __syncthreads();

    int NP = nph + 16;
    for (int P = 0; P < NP; P++) {
        int q = P - w;
        if (q >= 0 && q < nph) {
            int j0 = q << 3;

            // prefetch phase q+2 (consumed 2 phases later)
            float c2[8];
            #pragma unroll
            for (int d = 0; d < 8; d++) {
                int jj = j0 + 16 + d;
                c2[d] = (jj < ylen) ? base[(size_t)jj*TXn] : 0.f;
            }

            // neighbor boundary values for these 8 columns (stable this phase)
            float rb[8];
            if (w > 0) {
                #pragma unroll
                for (int d = 0; d < 8; d++) rb[d] = sbuf[w-1][(j0 + d) & 31];
            }

            #pragma unroll
            for (int d = 0; d < 8; d++) {
                int j = j0 + d;
                if (j < ylen) {                        // warp-uniform
                    float left = __shfl_up_sync(0xFFFFFFFFu, v, 1);
                    if (lane == 0) left = (w == 0) ? NEGV : rb[d];

                    bool  di = v >= left;
                    float nv = (di ? v : left) + cc[d];
                    if (x > j) nv = NEGV;

                    unsigned bits = __ballot_sync(0xFFFFFFFFu, di) | force;
                    if (lane == 0) dbase[(size_t)j*16] = bits;

                    v = nv;
                    if (lane == 31) sbuf[w][(j + 1) & 31] = v;
                }
            }

            #pragma unroll
            for (int d = 0; d < 8; d++) { cc[d] = cn[d]; cn[d] = c2[d]; }
        }
        __syncthreads();
    }
}

// -------------------- K5: backtrack + count (1 warp per batch, 32-bit words) ---
__global__ void __launch_bounds__(32)
bwd_kernel(const int* __restrict__ xl, const int* __restrict__ yl)
{
    int b = blockIdx.x, lane = threadIdx.x;
    int xlen = xl[b], ylen = yl[b];

    for (int j = ylen + lane; j < TYn; j += 32) g_xy[b*TYn + j] = 0;

    int idx = xlen - 1;
    for (int jhi = ylen - 1; jhi >= 0; jhi -= 32) {
        int steps = min(32, jhi + 1);
        int j = jhi - lane;
        int w0 = idx >> 5;                 // spans at most 2 words over 32 steps
        unsigned d0 = 0xFFFFFFFFu, d1 = 0xFFFFFFFFu;
        if (lane < steps) {
            const unsigned* p = g_dbits + ((size_t)b*TYn + j)*16;
            d0 = p[w0];
            if (w0 >= 1) d1 = p[w0-1];
        }
        int myidx = 0;
        for (int s = 0; s < steps; s++) {
            unsigned sel  = (w0 == (idx >> 5)) ? d0 : d1;
            unsigned word = __shfl_sync(0xFFFFFFFFu, sel, s);
            if (lane == s) myidx = idx;
            idx += (int)((word >> (idx & 31)) & 1u) - 1;
        }
        if (lane < steps) {
            g_xy[b*TYn + jhi - lane] = myidx;
            atomicAdd(&g_cnt[b*TXn + myidx], 1);
        }
    }
}

// -------------------- K6: y_mean / y_log_scale gathers -------------------------
__global__ void gather_kernel(const float* __restrict__ om,
                              const float* __restrict__ ols,
                              const int* __restrict__ yl,
                              float* __restrict__ out)
{
    int i = blockIdx.x * blockDim.x + threadIdx.x;
    if (i >= Bn*Cc*TYn) return;
    int b = i / (Cc*TYn);
    int r = i % (Cc*TYn);
    int c = r / TYn;
    int y = r % TYn;
    float m = 0.f, s = 0.f;
    if (y < yl[b]) {
        int x = g_xy[b*TYn + y];
        m = om [(size_t)(b*Cc + c)*TXn + x];
        s = ols[(size_t)(b*Cc + c)*TXn + x];
    }
    out[YMEAN_OFF + i] = m;
    out[YLOG_OFF  + i] = s;
}

// -------------------- K7: attn_out (zero + one-hot scatter) --------------------
__global__ void attn_kernel(const int* __restrict__ yl, float* __restrict__ out)
{
    int y = blockIdx.x, b = blockIdx.y, t = threadIdx.x;
    int xi = (y < yl[b]) ? g_xy[b*TYn + y] : -1;
    int x4 = t << 2;
    float4 r = make_float4(0.f, 0.f, 0.f, 0.f);
    if (xi >= x4 && xi < x4 + 4) ((float*)&r)[xi - x4] = 1.0f;
    *(float4*)&out[ATTN_OFF + ((size_t)b*TYn + y)*TXn + x4] = r;
}

// -------------------- K8: o_attn_dur --------------------------------------------
__global__ void dur_kernel(const int* __restrict__ xl, float* __restrict__ out)
{
    int i = blockIdx.x * blockDim.x + threadIdx.x;
    if (i >= Bn*TXn) return;
    int b = i / TXn, x = i % TXn;
    out[OADUR_OFF + i] = (x < xl[b]) ? log1pf((float)g_cnt[i]) : 0.f;
}

// -------------------- launch (single stream) -------------------------------------
extern "C" void kernel_launch(void* const* d_in, const int* in_sizes, int n_in,
                              void* d_out, int out_size)
{
    const float* om   = (const float*)d_in[0];
    const float* ols  = (const float*)d_in[1];
    const float* odur = (const float*)d_in[2];
    const float* z    = (const float*)d_in[3];
    const int*   xlen = (const int*)  d_in[4];
    const int*   ylen = (const int*)  d_in[5];
    float* out = (float*)d_out;

    prepx_kernel<<<(Bn*TXn + 255)/256, 256>>>(om, ols, odur, out);
    prepz_kernel<<<(Bn*Cc*TYn + 255)/256, 256>>>(z, ylen, out);
    gemm_kernel<<<dim3(TXn/128, TYn/128, Bn), 256>>>(xlen, ylen);
    fwd_kernel<<<Bn, 512>>>(xlen, ylen);
    bwd_kernel<<<Bn, 32>>>(xlen, ylen);
    gather_kernel<<<(Bn*Cc*TYn + 255)/256, 256>>>(om, ols, ylen, out);
    attn_kernel<<<dim3(TYn, Bn), 128>>>(ylen, out);
    dur_kernel<<<(Bn*TXn + 255)/256, 256>>>(xlen, out);
}